// round 6
// baseline (speedup 1.0000x reference)
#include <cuda_runtime.h>
#include <cuda_fp16.h>
#include <cstdint>

#define N_NODES 50000
#define E_EDGES 800000
#define IN_DIM  128
#define H_DIM   96
#define OUT_DIM 64
#define NUM_LAYERS 4
#define NB_SCAN ((N_NODES + 1023) / 1024)
#define HWORDS  48   // 96 channels as half2 words

// ---------------- static device scratch ----------------
__device__ float    g_hfin[N_NODES * H_DIM];                   // final-layer fp32 h
__device__ uint32_t g_hhalf[(size_t)N_NODES * HWORDS + 16];    // fp16 h (+pad for lane shadow)
__device__ float    g_agg[(size_t)N_NODES * 2 * H_DIM];
__device__ int      g_counts[N_NODES];
__device__ int      g_offsets[N_NODES + 1];
__device__ int      g_cursor[N_NODES];
__device__ int      g_src_sorted[E_EDGES];
__device__ int      g_pos[E_EDGES];
__device__ float2   g_ews[(size_t)E_EDGES * NUM_LAYERS];
__device__ int      g_bsum[NB_SCAN + 1];
__device__ float    g_zero_bias[H_DIM];

// ---------------- f32x2 packed helpers ----------------
__device__ __forceinline__ double pack2(float lo, float hi) {
    double d;
    asm("mov.b64 %0, {%1, %2};" : "=d"(d) : "f"(lo), "f"(hi));
    return d;
}
__device__ __forceinline__ void fma2(double& acc, double a, double b) {
    asm("fma.rn.f32x2 %0, %1, %2, %0;" : "+d"(acc) : "d"(a), "d"(b));
}
__device__ __forceinline__ float2 unpack2(double d) {
    float lo, hi;
    asm("mov.b64 {%0, %1}, %2;" : "=f"(lo), "=f"(hi) : "d"(d));
    return make_float2(lo, hi);
}

// ---------------- CSR build ----------------
__global__ void hist_kernel(const int* __restrict__ dst) {
    int e = blockIdx.x * blockDim.x + threadIdx.x;
    if (e < E_EDGES) atomicAdd(&g_counts[dst[e]], 1);
}

__global__ void block_scan_kernel() {
    __shared__ int sh[1024];
    int t = threadIdx.x;
    int i = blockIdx.x * 1024 + t;
    int v = (i < N_NODES) ? g_counts[i] : 0;
    sh[t] = v;
    __syncthreads();
    #pragma unroll
    for (int off = 1; off < 1024; off <<= 1) {
        int x = (t >= off) ? sh[t - off] : 0;
        __syncthreads();
        sh[t] += x;
        __syncthreads();
    }
    if (i < N_NODES) g_offsets[i] = sh[t] - v;
    if (t == 1023) g_bsum[blockIdx.x] = sh[1023];
}

__global__ void add_base_kernel() {
    __shared__ int pref[NB_SCAN + 1];
    if (threadIdx.x == 0) {
        int run = 0;
        #pragma unroll
        for (int i = 0; i < NB_SCAN; i++) { pref[i] = run; run += g_bsum[i]; }
        pref[NB_SCAN] = run;
    }
    __syncthreads();
    int i = blockIdx.x * blockDim.x + threadIdx.x;
    if (i < N_NODES) {
        int o = g_offsets[i] + pref[i >> 10];
        g_offsets[i] = o;
        g_cursor[i] = o;
    }
    if (i == N_NODES) g_offsets[N_NODES] = pref[NB_SCAN];
}

// light scatter: permutation + layer-0 weights only
__global__ void scatter_light_kernel(const int* __restrict__ src,
                                     const int* __restrict__ dst,
                                     const float* __restrict__ conv_ew) {
    int e = blockIdx.x * blockDim.x + threadIdx.x;
    if (e >= E_EDGES) return;
    int d = dst[e];
    int pos = atomicAdd(&g_cursor[d], 1);
    g_src_sorted[pos] = src[e];
    g_pos[e] = pos;
    g_ews[(size_t)pos * NUM_LAYERS] = make_float2(conv_ew[e], conv_ew[E_EDGES + e]);
}

// layers 1..3 weights (runs on side stream, overlapped)
__global__ void ews_rest_kernel(const float* __restrict__ conv_ew) {
    int e = blockIdx.x * blockDim.x + threadIdx.x;
    if (e >= E_EDGES) return;
    int pos = g_pos[e];
    #pragma unroll
    for (int l = 1; l < NUM_LAYERS; l++) {
        float w0 = conv_ew[(size_t)(l * 2 + 0) * E_EDGES + e];
        float w1 = conv_ew[(size_t)(l * 2 + 1) * E_EDGES + e];
        g_ews[(size_t)pos * NUM_LAYERS + l] = make_float2(w0, w1);
    }
}

// ---------------- register-tiled fp32 GEMM, packed f32x2 FMA, pre-packed B ----------------
// BM=64, BN=TN*16, BK=16, 128 threads, per-thread 8(M) x TN(N).
template <int TN, bool RELU, bool WF32, bool WHALF>
__global__ void __launch_bounds__(128)
gemm_kernel(const float* __restrict__ A, const float* __restrict__ B,
            const float* __restrict__ bias, float* __restrict__ C,
            uint32_t* __restrict__ Chalf, float* __restrict__ C2,
            int M, int K, int lda, int ldc) {
    constexpr int BN = TN * 16;
    constexpr int BM = 64;
    constexpr int BK = 16;
    constexpr int TM = 8;
    __shared__ __align__(16) float  As[BK][BM + 4];
    __shared__ __align__(16) double Bs[BK][BN];   // each entry = (b,b) packed f32x2

    int tid = threadIdx.x;
    int tx = tid & 15;
    int ty = tid >> 4;
    int blockRow = blockIdx.x * BM;

    double acc[TM / 2][TN];
    #pragma unroll
    for (int i = 0; i < TM / 2; i++)
        #pragma unroll
        for (int j = 0; j < TN; j++) acc[i][j] = 0.0;

    for (int k0 = 0; k0 < K; k0 += BK) {
        // A tile: 64x16 floats = 256 float4, transpose into As[k][m]
        #pragma unroll
        for (int r = 0; r < 2; r++) {
            int f = tid + r * 128;
            int row = f >> 2;
            int seg = f & 3;
            int gRow = blockRow + row;
            float4 v = make_float4(0.f, 0.f, 0.f, 0.f);
            if (gRow < M) v = *(const float4*)(A + (size_t)gRow * lda + k0 + seg * 4);
            As[seg * 4 + 0][row] = v.x;
            As[seg * 4 + 1][row] = v.y;
            As[seg * 4 + 2][row] = v.z;
            As[seg * 4 + 3][row] = v.w;
        }
        // B tile (ldb == BN): load float4, store duplicated packs
        #pragma unroll
        for (int e = tid; e < BK * BN / 4; e += 128) {
            float4 v = ((const float4*)(B + (size_t)k0 * BN))[e];
            int idx = e * 4;
            int row = idx / BN, col = idx % BN;
            double2* p = (double2*)&Bs[row][col];
            p[0] = make_double2(pack2(v.x, v.x), pack2(v.y, v.y));
            p[1] = make_double2(pack2(v.z, v.z), pack2(v.w, v.w));
        }
        __syncthreads();
        #pragma unroll
        for (int kk = 0; kk < BK; kk++) {
            double2 A01 = *(const double2*)&As[kk][ty * TM];
            double2 A23 = *(const double2*)&As[kk][ty * TM + 4];
            double a2[TM / 2] = {A01.x, A01.y, A23.x, A23.y};
            double b2[TN];
            #pragma unroll
            for (int j = 0; j < TN / 2; j++) {
                double2 t = *(const double2*)&Bs[kk][tx * TN + 2 * j];
                b2[2 * j] = t.x; b2[2 * j + 1] = t.y;
            }
            #pragma unroll
            for (int i = 0; i < TM / 2; i++)
                #pragma unroll
                for (int j = 0; j < TN; j++) fma2(acc[i][j], a2[i], b2[j]);
        }
        __syncthreads();
    }

    #pragma unroll
    for (int i = 0; i < TM / 2; i++) {
        float2 col[TN];
        #pragma unroll
        for (int j = 0; j < TN; j++) col[j] = unpack2(acc[i][j]);
        #pragma unroll
        for (int half = 0; half < 2; half++) {
            int gRow = blockRow + ty * TM + 2 * i + half;
            if (gRow >= M) continue;
            float v[TN];
            #pragma unroll
            for (int j = 0; j < TN; j++) {
                float t = (half ? col[j].y : col[j].x) + bias[tx * TN + j];
                v[j] = RELU ? fmaxf(t, 0.f) : t;
            }
            if (WF32) {
                float* crow = C + (size_t)gRow * ldc + tx * TN;
                #pragma unroll
                for (int j = 0; j < TN / 2; j++)
                    *(float2*)(crow + 2 * j) = make_float2(v[2 * j], v[2 * j + 1]);
                if (C2) {
                    float* c2row = C2 + (size_t)gRow * ldc + tx * TN;
                    #pragma unroll
                    for (int j = 0; j < TN / 2; j++)
                        *(float2*)(c2row + 2 * j) = make_float2(v[2 * j], v[2 * j + 1]);
                }
            }
            if (WHALF && TN == 6) {
                uint32_t* hrow = Chalf + (size_t)gRow * HWORDS + tx * 3;
                #pragma unroll
                for (int j = 0; j < 3; j++) {
                    __half2 hv = __float22half2_rn(make_float2(v[2 * j], v[2 * j + 1]));
                    hrow[j] = *(uint32_t*)&hv;
                }
            }
        }
    }
}

// ---------------- aggregation: warp/node, 24 lanes x 4 channels, packed FMA ----------------
__global__ void aggregate_kernel(const uint32_t* __restrict__ hh, int layer,
                                 float* __restrict__ agg) {
    int warp = (blockIdx.x * blockDim.x + threadIdx.x) >> 5;
    int lane = threadIdx.x & 31;
    if (warp >= N_NODES) return;
    int beg = g_offsets[warp];
    int end = g_offsets[warp + 1];
    int laneC = (lane < 24) ? lane : 0;   // lanes 24-31 shadow lane 0 (results discarded)

    double accA0 = 0.0, accA1 = 0.0, accB0 = 0.0, accB1 = 0.0;
    int j = beg;
    for (; j + 3 < end; j += 4) {
        int s0 = g_src_sorted[j],     s1 = g_src_sorted[j + 1];
        int s2 = g_src_sorted[j + 2], s3 = g_src_sorted[j + 3];
        float2 w0 = g_ews[(size_t)j * NUM_LAYERS + layer];
        float2 w1 = g_ews[(size_t)(j + 1) * NUM_LAYERS + layer];
        float2 w2 = g_ews[(size_t)(j + 2) * NUM_LAYERS + layer];
        float2 w3 = g_ews[(size_t)(j + 3) * NUM_LAYERS + layer];
        uint2 u0 = *(const uint2*)(hh + (size_t)s0 * HWORDS + 2 * laneC);
        uint2 u1 = *(const uint2*)(hh + (size_t)s1 * HWORDS + 2 * laneC);
        uint2 u2 = *(const uint2*)(hh + (size_t)s2 * HWORDS + 2 * laneC);
        uint2 u3 = *(const uint2*)(hh + (size_t)s3 * HWORDS + 2 * laneC);
        {
            float2 x0 = __half22float2(*(__half2*)&u0.x);
            float2 x1 = __half22float2(*(__half2*)&u0.y);
            double dx0 = pack2(x0.x, x0.y), dx1 = pack2(x1.x, x1.y);
            double wa = pack2(w0.x, w0.x), wb = pack2(w0.y, w0.y);
            fma2(accA0, dx0, wa); fma2(accA1, dx1, wa);
            fma2(accB0, dx0, wb); fma2(accB1, dx1, wb);
        }
        {
            float2 x0 = __half22float2(*(__half2*)&u1.x);
            float2 x1 = __half22float2(*(__half2*)&u1.y);
            double dx0 = pack2(x0.x, x0.y), dx1 = pack2(x1.x, x1.y);
            double wa = pack2(w1.x, w1.x), wb = pack2(w1.y, w1.y);
            fma2(accA0, dx0, wa); fma2(accA1, dx1, wa);
            fma2(accB0, dx0, wb); fma2(accB1, dx1, wb);
        }
        {
            float2 x0 = __half22float2(*(__half2*)&u2.x);
            float2 x1 = __half22float2(*(__half2*)&u2.y);
            double dx0 = pack2(x0.x, x0.y), dx1 = pack2(x1.x, x1.y);
            double wa = pack2(w2.x, w2.x), wb = pack2(w2.y, w2.y);
            fma2(accA0, dx0, wa); fma2(accA1, dx1, wa);
            fma2(accB0, dx0, wb); fma2(accB1, dx1, wb);
        }
        {
            float2 x0 = __half22float2(*(__half2*)&u3.x);
            float2 x1 = __half22float2(*(__half2*)&u3.y);
            double dx0 = pack2(x0.x, x0.y), dx1 = pack2(x1.x, x1.y);
            double wa = pack2(w3.x, w3.x), wb = pack2(w3.y, w3.y);
            fma2(accA0, dx0, wa); fma2(accA1, dx1, wa);
            fma2(accB0, dx0, wb); fma2(accB1, dx1, wb);
        }
    }
    for (; j < end; j++) {
        int s = g_src_sorted[j];
        float2 w = g_ews[(size_t)j * NUM_LAYERS + layer];
        uint2 u = *(const uint2*)(hh + (size_t)s * HWORDS + 2 * laneC);
        float2 x0 = __half22float2(*(__half2*)&u.x);
        float2 x1 = __half22float2(*(__half2*)&u.y);
        double dx0 = pack2(x0.x, x0.y), dx1 = pack2(x1.x, x1.y);
        double wa = pack2(w.x, w.x), wb = pack2(w.y, w.y);
        fma2(accA0, dx0, wa); fma2(accA1, dx1, wa);
        fma2(accB0, dx0, wb); fma2(accB1, dx1, wb);
    }
    if (lane < 24) {
        float* o = agg + (size_t)warp * (2 * H_DIM);
        float2 a0 = unpack2(accA0), a1 = unpack2(accA1);
        float2 b0 = unpack2(accB0), b1 = unpack2(accB1);
        *(float4*)(o + 4 * lane)          = make_float4(a0.x, a0.y, a1.x, a1.y);
        *(float4*)(o + 96 + 4 * lane)     = make_float4(b0.x, b0.y, b1.x, b1.y);
    }
}

// ---------------- launch ----------------
extern "C" void kernel_launch(void* const* d_in, const int* in_sizes, int n_in,
                              void* d_out, int out_size) {
    const float* x       = (const float*)d_in[0];
    const int*   eidx    = (const int*)d_in[1];
    const float* enc_w   = (const float*)d_in[2];
    const float* enc_b   = (const float*)d_in[3];
    const float* dec_w   = (const float*)d_in[4];
    const float* dec_b   = (const float*)d_in[5];
    const float* conv_W  = (const float*)d_in[6];
    const float* conv_ew = (const float*)d_in[7];
    float* out = (float*)d_out;

    const int* src = eidx;
    const int* dst = eidx + E_EDGES;

    void *p_hfin, *p_hh, *p_agg, *p_zb, *p_counts;
    cudaGetSymbolAddress(&p_hfin, g_hfin);
    cudaGetSymbolAddress(&p_hh, g_hhalf);
    cudaGetSymbolAddress(&p_agg, g_agg);
    cudaGetSymbolAddress(&p_zb, g_zero_bias);
    cudaGetSymbolAddress(&p_counts, g_counts);
    float* hfin = (float*)p_hfin;
    uint32_t* hh = (uint32_t*)p_hh;
    float* agg = (float*)p_agg;
    const float* zb = (const float*)p_zb;

    // one-time host resources (no device allocations)
    static cudaStream_t sB = nullptr;
    static cudaEvent_t evStart, evEnc, evScat, evB;
    if (!sB) {
        cudaStreamCreateWithFlags(&sB, cudaStreamNonBlocking);
        cudaEventCreateWithFlags(&evStart, cudaEventDisableTiming);
        cudaEventCreateWithFlags(&evEnc, cudaEventDisableTiming);
        cudaEventCreateWithFlags(&evScat, cudaEventDisableTiming);
        cudaEventCreateWithFlags(&evB, cudaEventDisableTiming);
    }

    int gemmGrid = (N_NODES + 63) / 64;

    // ---- fork: encoder GEMM on side stream ----
    cudaEventRecord(evStart, 0);
    cudaStreamWaitEvent(sB, evStart, 0);
    gemm_kernel<6, true, false, true><<<gemmGrid, 128, 0, sB>>>(
        x, enc_w, enc_b, nullptr, hh, nullptr, N_NODES, IN_DIM, IN_DIM, H_DIM);
    cudaEventRecord(evEnc, sB);

    // ---- main stream: CSR build ----
    cudaMemsetAsync(p_counts, 0, N_NODES * sizeof(int), 0);
    hist_kernel<<<(E_EDGES + 255) / 256, 256>>>(dst);
    block_scan_kernel<<<NB_SCAN, 1024>>>();
    add_base_kernel<<<(N_NODES + 256) / 256, 256>>>();
    scatter_light_kernel<<<(E_EDGES + 255) / 256, 256>>>(src, dst, conv_ew);
    cudaEventRecord(evScat, 0);

    // side stream: remaining layer weights (overlaps agg0/gemm0)
    cudaStreamWaitEvent(sB, evScat, 0);
    ews_rest_kernel<<<(E_EDGES + 255) / 256, 256, 0, sB>>>(conv_ew);
    cudaEventRecord(evB, sB);

    // ---- layers ----
    cudaStreamWaitEvent(0, evEnc, 0);
    // layer 0
    aggregate_kernel<<<(N_NODES * 32 + 255) / 256, 256>>>(hh, 0, agg);
    gemm_kernel<6, true, false, true><<<gemmGrid, 128>>>(
        agg, conv_W, zb, nullptr, hh, nullptr, N_NODES, 2 * H_DIM, 2 * H_DIM, H_DIM);
    cudaStreamWaitEvent(0, evB, 0);
    // layers 1..2
    for (int l = 1; l < NUM_LAYERS - 1; l++) {
        aggregate_kernel<<<(N_NODES * 32 + 255) / 256, 256>>>(hh, l, agg);
        gemm_kernel<6, true, false, true><<<gemmGrid, 128>>>(
            agg, conv_W + (size_t)l * 2 * H_DIM * H_DIM, zb, nullptr, hh, nullptr,
            N_NODES, 2 * H_DIM, 2 * H_DIM, H_DIM);
    }
    // layer 3: fp32 h + duplicate to out tail
    aggregate_kernel<<<(N_NODES * 32 + 255) / 256, 256>>>(hh, NUM_LAYERS - 1, agg);
    gemm_kernel<6, true, true, false><<<gemmGrid, 128>>>(
        agg, conv_W + (size_t)(NUM_LAYERS - 1) * 2 * H_DIM * H_DIM, zb, hfin, nullptr,
        out + (size_t)N_NODES * OUT_DIM, N_NODES, 2 * H_DIM, 2 * H_DIM, H_DIM);

    // decoder
    gemm_kernel<4, false, true, false><<<gemmGrid, 128>>>(
        hfin, dec_w, dec_b, out, nullptr, nullptr, N_NODES, H_DIM, H_DIM, OUT_DIM);
    (void)in_sizes; (void)n_in; (void)out_size;
}

// round 7
// speedup vs baseline: 1.2047x; 1.2047x over previous
#include <cuda_runtime.h>
#include <cuda_fp16.h>
#include <cstdint>

#define N_NODES 50000
#define E_EDGES 800000
#define IN_DIM  128
#define H_DIM   96
#define OUT_DIM 64
#define NUM_LAYERS 4
#define NB_SCAN ((N_NODES + 1023) / 1024)
#define HWORDS  48   // 96 channels as half2 words

// ---------------- static device scratch ----------------
__device__ float    g_hfin[N_NODES * H_DIM];                 // final-layer fp32 h
__device__ uint32_t g_hhalf[(size_t)N_NODES * HWORDS];       // h as half2 words
__device__ float    g_agg[(size_t)N_NODES * 2 * H_DIM];
__device__ int      g_counts[N_NODES];
__device__ int      g_offsets[N_NODES + 1];
__device__ int      g_cursor[N_NODES];
__device__ int      g_src_sorted[E_EDGES];
__device__ float2   g_ews[(size_t)E_EDGES * NUM_LAYERS];
__device__ int      g_bsum[NB_SCAN + 1];
__device__ float    g_zero_bias[H_DIM];

// ---------------- f32x2 packed helpers ----------------
__device__ __forceinline__ double pack2(float lo, float hi) {
    double d;
    asm("mov.b64 %0, {%1, %2};" : "=d"(d) : "f"(lo), "f"(hi));
    return d;
}
__device__ __forceinline__ void fma2(double& acc, double a, double b) {
    asm("fma.rn.f32x2 %0, %1, %2, %0;" : "+d"(acc) : "d"(a), "d"(b));
}
__device__ __forceinline__ float2 unpack2(double d) {
    float lo, hi;
    asm("mov.b64 {%0, %1}, %2;" : "=f"(lo), "=f"(hi) : "d"(d));
    return make_float2(lo, hi);
}

// ---------------- CSR build ----------------
__global__ void hist_kernel(const int* __restrict__ dst) {
    int e = blockIdx.x * blockDim.x + threadIdx.x;
    if (e < E_EDGES) atomicAdd(&g_counts[dst[e]], 1);
}

__global__ void block_scan_kernel() {
    __shared__ int sh[1024];
    int t = threadIdx.x;
    int i = blockIdx.x * 1024 + t;
    int v = (i < N_NODES) ? g_counts[i] : 0;
    sh[t] = v;
    __syncthreads();
    #pragma unroll
    for (int off = 1; off < 1024; off <<= 1) {
        int x = (t >= off) ? sh[t - off] : 0;
        __syncthreads();
        sh[t] += x;
        __syncthreads();
    }
    if (i < N_NODES) g_offsets[i] = sh[t] - v;
    if (t == 1023) g_bsum[blockIdx.x] = sh[1023];
}

__global__ void add_base_kernel() {
    __shared__ int pref[NB_SCAN + 1];
    if (threadIdx.x == 0) {
        int run = 0;
        #pragma unroll
        for (int i = 0; i < NB_SCAN; i++) { pref[i] = run; run += g_bsum[i]; }
        pref[NB_SCAN] = run;
    }
    __syncthreads();
    int i = blockIdx.x * blockDim.x + threadIdx.x;
    if (i < N_NODES) {
        int o = g_offsets[i] + pref[i >> 10];
        g_offsets[i] = o;
        g_cursor[i] = o;
    }
    if (i == N_NODES) g_offsets[N_NODES] = pref[NB_SCAN];
}

__global__ void scatter_kernel(const int* __restrict__ src,
                               const int* __restrict__ dst,
                               const float* __restrict__ conv_ew) {
    int e = blockIdx.x * blockDim.x + threadIdx.x;
    if (e >= E_EDGES) return;
    int d = dst[e];
    int pos = atomicAdd(&g_cursor[d], 1);
    g_src_sorted[pos] = src[e];
    #pragma unroll
    for (int l = 0; l < NUM_LAYERS; l++) {
        float w0 = conv_ew[(size_t)(l * 2 + 0) * E_EDGES + e];
        float w1 = conv_ew[(size_t)(l * 2 + 1) * E_EDGES + e];
        g_ews[(size_t)pos * NUM_LAYERS + l] = make_float2(w0, w1);
    }
}

// ---------------- register-tiled fp32 GEMM, packed f32x2 FMA ----------------
// BM=64, BN=TN*16, BK=16, 128 threads, per-thread 8(M) x TN(N).
// WF32: write fp32 C (and optional C2 duplicate). WHALF: write half2-packed rows (TN==6).
template <int TN, bool RELU, bool WF32, bool WHALF>
__global__ void __launch_bounds__(128)
gemm_kernel(const float* __restrict__ A, const float* __restrict__ B,
            const float* __restrict__ bias, float* __restrict__ C,
            uint32_t* __restrict__ Chalf, float* __restrict__ C2,
            int M, int K, int lda, int ldc) {
    constexpr int BN = TN * 16;
    constexpr int BM = 64;
    constexpr int BK = 16;
    constexpr int TM = 8;
    __shared__ float As[BK][BM + 4];
    __shared__ float Bs[BK][BN];

    int tid = threadIdx.x;
    int tx = tid & 15;
    int ty = tid >> 4;
    int blockRow = blockIdx.x * BM;

    double acc[TM / 2][TN];
    #pragma unroll
    for (int i = 0; i < TM / 2; i++)
        #pragma unroll
        for (int j = 0; j < TN; j++) acc[i][j] = 0.0;

    for (int k0 = 0; k0 < K; k0 += BK) {
        // A tile: 64x16 floats = 256 float4, transpose into As[k][m]
        #pragma unroll
        for (int r = 0; r < 2; r++) {
            int f = tid + r * 128;
            int row = f >> 2;
            int seg = f & 3;
            int gRow = blockRow + row;
            float4 v = make_float4(0.f, 0.f, 0.f, 0.f);
            if (gRow < M) v = *(const float4*)(A + (size_t)gRow * lda + k0 + seg * 4);
            As[seg * 4 + 0][row] = v.x;
            As[seg * 4 + 1][row] = v.y;
            As[seg * 4 + 2][row] = v.z;
            As[seg * 4 + 3][row] = v.w;
        }
        // B tile (ldb == BN): contiguous float4 copy
        #pragma unroll
        for (int e = tid; e < BK * BN / 4; e += 128)
            ((float4*)Bs)[e] = ((const float4*)(B + (size_t)k0 * BN))[e];
        __syncthreads();
        #pragma unroll
        for (int kk = 0; kk < BK; kk++) {
            double a2[TM / 2];
            #pragma unroll
            for (int i = 0; i < TM / 2; i++)
                a2[i] = *(const double*)&As[kk][ty * TM + 2 * i];
            double b2[TN];
            #pragma unroll
            for (int j = 0; j < TN / 2; j++) {
                float2 t2 = *(const float2*)&Bs[kk][tx * TN + 2 * j];
                b2[2 * j + 0] = pack2(t2.x, t2.x);
                b2[2 * j + 1] = pack2(t2.y, t2.y);
            }
            #pragma unroll
            for (int i = 0; i < TM / 2; i++)
                #pragma unroll
                for (int j = 0; j < TN; j++) fma2(acc[i][j], a2[i], b2[j]);
        }
        __syncthreads();
    }

    #pragma unroll
    for (int i = 0; i < TM / 2; i++) {
        float2 col[TN];
        #pragma unroll
        for (int j = 0; j < TN; j++) col[j] = unpack2(acc[i][j]);
        #pragma unroll
        for (int half = 0; half < 2; half++) {
            int gRow = blockRow + ty * TM + 2 * i + half;
            if (gRow >= M) continue;
            float v[TN];
            #pragma unroll
            for (int j = 0; j < TN; j++) {
                float t = (half ? col[j].y : col[j].x) + bias[tx * TN + j];
                v[j] = RELU ? fmaxf(t, 0.f) : t;
            }
            if (WF32) {
                float* crow = C + (size_t)gRow * ldc + tx * TN;
                #pragma unroll
                for (int j = 0; j < TN / 2; j++)
                    *(float2*)(crow + 2 * j) = make_float2(v[2 * j], v[2 * j + 1]);
                if (C2) {
                    float* c2row = C2 + (size_t)gRow * ldc + tx * TN;
                    #pragma unroll
                    for (int j = 0; j < TN / 2; j++)
                        *(float2*)(c2row + 2 * j) = make_float2(v[2 * j], v[2 * j + 1]);
                }
            }
            if (WHALF && TN == 6) {
                uint32_t* hrow = Chalf + (size_t)gRow * HWORDS + tx * 3;
                #pragma unroll
                for (int j = 0; j < 3; j++) {
                    __half2 hv = __float22half2_rn(make_float2(v[2 * j], v[2 * j + 1]));
                    hrow[j] = *(uint32_t*)&hv;
                }
            }
        }
    }
}

// ---------------- per-node aggregation over fp16 h (warp per node) ----------------
// lane covers channels {2*lane, 2*lane+1}; lanes 0-15 additionally {64+2*lane, 65+2*lane}.
__global__ void aggregate_kernel(const uint32_t* __restrict__ hh, int layer,
                                 float* __restrict__ agg) {
    int warp = (blockIdx.x * blockDim.x + threadIdx.x) >> 5;
    int lane = threadIdx.x & 31;
    if (warp >= N_NODES) return;
    int beg = g_offsets[warp];
    int end = g_offsets[warp + 1];
    bool lo = lane < 16;

    float2 A0 = {0.f, 0.f}, B0 = {0.f, 0.f};
    float2 A1 = {0.f, 0.f}, B1 = {0.f, 0.f};
    int j = beg;
    for (; j + 3 < end; j += 4) {
        int s0 = g_src_sorted[j],     s1 = g_src_sorted[j + 1];
        int s2 = g_src_sorted[j + 2], s3 = g_src_sorted[j + 3];
        float2 w0 = g_ews[(size_t)j * NUM_LAYERS + layer];
        float2 w1 = g_ews[(size_t)(j + 1) * NUM_LAYERS + layer];
        float2 w2 = g_ews[(size_t)(j + 2) * NUM_LAYERS + layer];
        float2 w3 = g_ews[(size_t)(j + 3) * NUM_LAYERS + layer];
        const uint32_t* r0 = hh + (size_t)s0 * HWORDS;
        const uint32_t* r1 = hh + (size_t)s1 * HWORDS;
        const uint32_t* r2 = hh + (size_t)s2 * HWORDS;
        const uint32_t* r3 = hh + (size_t)s3 * HWORDS;
        uint32_t u00 = r0[lane], u10 = r1[lane], u20 = r2[lane], u30 = r3[lane];
        uint32_t u01 = lo ? r0[32 + lane] : 0;
        uint32_t u11 = lo ? r1[32 + lane] : 0;
        uint32_t u21 = lo ? r2[32 + lane] : 0;
        uint32_t u31 = lo ? r3[32 + lane] : 0;
        float2 x;
        x = __half22float2(*(__half2*)&u00);
        A0.x += w0.x * x.x; A0.y += w0.x * x.y; B0.x += w0.y * x.x; B0.y += w0.y * x.y;
        x = __half22float2(*(__half2*)&u10);
        A0.x += w1.x * x.x; A0.y += w1.x * x.y; B0.x += w1.y * x.x; B0.y += w1.y * x.y;
        x = __half22float2(*(__half2*)&u20);
        A0.x += w2.x * x.x; A0.y += w2.x * x.y; B0.x += w2.y * x.x; B0.y += w2.y * x.y;
        x = __half22float2(*(__half2*)&u30);
        A0.x += w3.x * x.x; A0.y += w3.x * x.y; B0.x += w3.y * x.x; B0.y += w3.y * x.y;
        x = __half22float2(*(__half2*)&u01);
        A1.x += w0.x * x.x; A1.y += w0.x * x.y; B1.x += w0.y * x.x; B1.y += w0.y * x.y;
        x = __half22float2(*(__half2*)&u11);
        A1.x += w1.x * x.x; A1.y += w1.x * x.y; B1.x += w1.y * x.x; B1.y += w1.y * x.y;
        x = __half22float2(*(__half2*)&u21);
        A1.x += w2.x * x.x; A1.y += w2.x * x.y; B1.x += w2.y * x.x; B1.y += w2.y * x.y;
        x = __half22float2(*(__half2*)&u31);
        A1.x += w3.x * x.x; A1.y += w3.x * x.y; B1.x += w3.y * x.x; B1.y += w3.y * x.y;
    }
    for (; j < end; j++) {
        int s = g_src_sorted[j];
        float2 w = g_ews[(size_t)j * NUM_LAYERS + layer];
        const uint32_t* r = hh + (size_t)s * HWORDS;
        uint32_t u0 = r[lane];
        uint32_t u1 = lo ? r[32 + lane] : 0;
        float2 x = __half22float2(*(__half2*)&u0);
        A0.x += w.x * x.x; A0.y += w.x * x.y; B0.x += w.y * x.x; B0.y += w.y * x.y;
        x = __half22float2(*(__half2*)&u1);
        A1.x += w.x * x.x; A1.y += w.x * x.y; B1.x += w.y * x.x; B1.y += w.y * x.y;
    }
    float* o = agg + (size_t)warp * (2 * H_DIM);
    *(float2*)(o + 2 * lane)       = A0;
    *(float2*)(o + 96 + 2 * lane)  = B0;
    if (lo) {
        *(float2*)(o + 64 + 2 * lane)  = A1;
        *(float2*)(o + 160 + 2 * lane) = B1;
    }
}

// ---------------- launch ----------------
extern "C" void kernel_launch(void* const* d_in, const int* in_sizes, int n_in,
                              void* d_out, int out_size) {
    const float* x       = (const float*)d_in[0];
    const int*   eidx    = (const int*)d_in[1];
    const float* enc_w   = (const float*)d_in[2];
    const float* enc_b   = (const float*)d_in[3];
    const float* dec_w   = (const float*)d_in[4];
    const float* dec_b   = (const float*)d_in[5];
    const float* conv_W  = (const float*)d_in[6];
    const float* conv_ew = (const float*)d_in[7];
    float* out = (float*)d_out;

    const int* src = eidx;
    const int* dst = eidx + E_EDGES;

    void *p_hfin, *p_hh, *p_agg, *p_zb, *p_counts;
    cudaGetSymbolAddress(&p_hfin, g_hfin);
    cudaGetSymbolAddress(&p_hh, g_hhalf);
    cudaGetSymbolAddress(&p_agg, g_agg);
    cudaGetSymbolAddress(&p_zb, g_zero_bias);
    cudaGetSymbolAddress(&p_counts, g_counts);
    float* hfin = (float*)p_hfin;
    uint32_t* hh = (uint32_t*)p_hh;
    float* agg = (float*)p_agg;
    const float* zb = (const float*)p_zb;

    // CSR build
    cudaMemsetAsync(p_counts, 0, N_NODES * sizeof(int));
    hist_kernel<<<(E_EDGES + 255) / 256, 256>>>(dst);
    block_scan_kernel<<<NB_SCAN, 1024>>>();
    add_base_kernel<<<(N_NODES + 256) / 256, 256>>>();
    scatter_kernel<<<(E_EDGES + 255) / 256, 256>>>(src, dst, conv_ew);

    int gemmGrid = (N_NODES + 63) / 64;

    // encoder: fp16 h only (fp32 copy is dead)
    gemm_kernel<6, true, false, true><<<gemmGrid, 128>>>(
        x, enc_w, enc_b, nullptr, hh, nullptr, N_NODES, IN_DIM, IN_DIM, H_DIM);

    // layers 0..2: fp16 h only
    for (int l = 0; l < NUM_LAYERS - 1; l++) {
        aggregate_kernel<<<(N_NODES * 32 + 255) / 256, 256>>>(hh, l, agg);
        gemm_kernel<6, true, false, true><<<gemmGrid, 128>>>(
            agg, conv_W + (size_t)l * 2 * H_DIM * H_DIM, zb, nullptr, hh, nullptr,
            N_NODES, 2 * H_DIM, 2 * H_DIM, H_DIM);
    }
    // layer 3: fp32 h for decoder + duplicate into out tail
    aggregate_kernel<<<(N_NODES * 32 + 255) / 256, 256>>>(hh, NUM_LAYERS - 1, agg);
    gemm_kernel<6, true, true, false><<<gemmGrid, 128>>>(
        agg, conv_W + (size_t)(NUM_LAYERS - 1) * 2 * H_DIM * H_DIM, zb, hfin, nullptr,
        out + (size_t)N_NODES * OUT_DIM, N_NODES, 2 * H_DIM, 2 * H_DIM, H_DIM);

    // decoder
    gemm_kernel<4, false, true, false><<<gemmGrid, 128>>>(
        hfin, dec_w, dec_b, out, nullptr, nullptr, N_NODES, H_DIM, H_DIM, OUT_DIM);
    (void)in_sizes; (void)n_in; (void)out_size;
}